// round 1
// baseline (speedup 1.0000x reference)
#include <cuda_runtime.h>
#include <math.h>
#include <stdint.h>

// ---------------- problem dims ----------------
#define BSZ   512
#define INDIM 4096
#define L1DIM 2048
#define DDIM  512
#define EDIM  64
#define KC    512                 // codebook size
#define NROWS (BSZ*DDIM)          // 262144
#define QDIM  (DDIM*EDIM)         // 32768

// ---------------- output layout (tuple flattened in order) ----------------
// (vq_loss, x_recon[512,4096], perplexity, q_st[512,32768], cls[512,10], zenc[512,512])
#define OFF_VQ   0
#define OFF_XREC 1
#define OFF_PPL  (1 + BSZ*INDIM)              // 2097153
#define OFF_QST  (OFF_PPL + 1)                // 2097154
#define OFF_CLS  (OFF_QST + BSZ*QDIM)         // 18874370
#define OFF_ZENC (OFF_CLS + BSZ*10)           // 18879490

// ---------------- device scratch (no runtime allocation allowed) ----------------
__device__ __align__(16) float g_h[BSZ*L1DIM];         // 4 MB
__device__ __align__(16) float g_z0[BSZ*DDIM];         // 1 MB
__device__ __align__(16) float g_e[(size_t)NROWS*EDIM];// 64 MB
__device__ __align__(16) float g_q[(size_t)NROWS*EDIM];// 64 MB (aligned copy of q_st)
__device__ __align__(16) int   g_idx[NROWS];
__device__ __align__(16) float g_counts[KC];
__device__ __align__(16) float g_part[1024];
__device__ __align__(16) float g_split[8*BSZ*DDIM];    // 8 MB split-K partials
__device__ __align__(16) float g_d1[BSZ*DDIM];
__device__ __align__(16) float g_d2[BSZ*DDIM];
__device__ __align__(16) float g_d3[BSZ*L1DIM];

// ================= generic tiled fp32 GEMM: C = [relu](A@W + b) =================
// A[M,K] row-major, W[K,N] row-major. 64x64 tile, TK=32, 256 threads, 4x4 microtile.
// If gridDim.z>1, writes raw partials (per split) instead; combine with splitk_reduce.
#define TM 64
#define TN 64
#define TK 32

__global__ __launch_bounds__(256) void gemm_kernel(
    const float* __restrict__ A, const float* __restrict__ W,
    const float* __restrict__ bias, float* __restrict__ C,
    float* __restrict__ part,
    int M, int N, int K, int kPerSplit, int doRelu)
{
    __shared__ float As[TK][TM + 4];
    __shared__ float Bs[TK][TN];
    const int tid = threadIdx.x;
    const int bm = blockIdx.y, bn = blockIdx.x, bz = blockIdx.z;
    const int splits = gridDim.z;
    const int kBeg = bz * kPerSplit;
    const int kEnd = kBeg + kPerSplit;

    float acc[4][4];
#pragma unroll
    for (int i = 0; i < 4; i++)
#pragma unroll
        for (int j = 0; j < 4; j++) acc[i][j] = 0.f;

    const int ty = tid >> 4, tx = tid & 15;

    for (int k0 = kBeg; k0 < kEnd; k0 += TK) {
        // load A tile 64x32 (transposed into smem)
#pragma unroll
        for (int q = tid; q < 512; q += 256) {
            int row = q >> 3, c8 = q & 7;
            float4 av = *(const float4*)(A + (size_t)(bm * TM + row) * K + k0 + c8 * 4);
            As[c8 * 4 + 0][row] = av.x;
            As[c8 * 4 + 1][row] = av.y;
            As[c8 * 4 + 2][row] = av.z;
            As[c8 * 4 + 3][row] = av.w;
        }
        // load B tile 32x64
#pragma unroll
        for (int q = tid; q < 512; q += 256) {
            int kr = q >> 4, nc = q & 15;
            *(float4*)(&Bs[kr][nc * 4]) =
                *(const float4*)(W + (size_t)(k0 + kr) * N + bn * TN + nc * 4);
        }
        __syncthreads();
#pragma unroll
        for (int kk = 0; kk < TK; kk++) {
            float4 a4 = *(const float4*)(&As[kk][ty * 4]);
            float4 b4 = *(const float4*)(&Bs[kk][tx * 4]);
            float a[4] = {a4.x, a4.y, a4.z, a4.w};
            float b[4] = {b4.x, b4.y, b4.z, b4.w};
#pragma unroll
            for (int i = 0; i < 4; i++)
#pragma unroll
                for (int j = 0; j < 4; j++) acc[i][j] = fmaf(a[i], b[j], acc[i][j]);
        }
        __syncthreads();
    }

    if (splits > 1) {
        float* P = part + (size_t)bz * M * N;
#pragma unroll
        for (int i = 0; i < 4; i++) {
            int m = bm * TM + ty * 4 + i;
#pragma unroll
            for (int j = 0; j < 4; j++) {
                int n = bn * TN + tx * 4 + j;
                P[(size_t)m * N + n] = acc[i][j];
            }
        }
    } else {
#pragma unroll
        for (int i = 0; i < 4; i++) {
            int m = bm * TM + ty * 4 + i;
#pragma unroll
            for (int j = 0; j < 4; j++) {
                int n = bn * TN + tx * 4 + j;
                float v = acc[i][j] + bias[n];
                if (doRelu) v = fmaxf(v, 0.f);
                C[(size_t)m * N + n] = v;
            }
        }
    }
}

__global__ void splitk_reduce(const float* __restrict__ part,
                              const float* __restrict__ bias,
                              float* __restrict__ C,
                              int MN, int N, int splits, int doRelu)
{
    int i = blockIdx.x * blockDim.x + threadIdx.x;
    if (i >= MN) return;
    float s = bias[i % N];
    for (int z = 0; z < splits; z++) s += part[(size_t)z * MN + i];
    if (doRelu) s = fmaxf(s, 0.f);
    C[i] = s;
}

// ================= residual block (Linear D->16, ReLU, Linear 16->D, ReLU, BN-eval, add) ===
__global__ __launch_bounds__(256) void resblock_kernel(
    const float* __restrict__ X,
    const float* __restrict__ W1, const float* __restrict__ b1,
    const float* __restrict__ W2, const float* __restrict__ b2,
    const float* __restrict__ g,  const float* __restrict__ beta,
    float* __restrict__ out)
{
    __shared__ float xr[DDIM];
    __shared__ float hp[16][17];
    __shared__ float hid[16];
    const int tid = threadIdx.x;
    const float* x = X + (size_t)blockIdx.x * DDIM;
    xr[tid] = x[tid];
    xr[tid + 256] = x[tid + 256];
    __syncthreads();

    int j = tid >> 4, s = tid & 15;
    float p = 0.f;
    int i0 = s * 32;
#pragma unroll 8
    for (int i = i0; i < i0 + 32; i++) p = fmaf(xr[i], W1[i * 16 + j], p);
    hp[j][s] = p;
    __syncthreads();
    if (tid < 16) {
        float v = b1[tid];
#pragma unroll
        for (int s2 = 0; s2 < 16; s2++) v += hp[tid][s2];
        hid[tid] = fmaxf(v, 0.f);
    }
    __syncthreads();

    const float inv = rsqrtf(1.0f + 1e-5f);
    for (int d = tid; d < DDIM; d += 256) {
        float u = b2[d];
#pragma unroll
        for (int j2 = 0; j2 < 16; j2++) u = fmaf(hid[j2], W2[j2 * DDIM + d], u);
        u = fmaxf(u, 0.f);
        out[(size_t)blockIdx.x * DDIM + d] = xr[d] + u * inv * g[d] + beta[d];
    }
}

// ================= per-scalar expansion MLP: e[b,d,:] = relu(z*Wt1+bt1)@Wt2 + bt2 ====
__global__ __launch_bounds__(256) void expand_kernel(
    const float* __restrict__ zenc,
    const float* __restrict__ Wt1, const float* __restrict__ bt1,
    const float* __restrict__ Wt2, const float* __restrict__ bt2,
    float* __restrict__ e)
{
    __shared__ float w1[32], bb1[32], w2[32 * 64], bb2[64];
    const int tid = threadIdx.x;
    if (tid < 32) { w1[tid] = Wt1[tid]; bb1[tid] = bt1[tid]; }
    if (tid < 64) bb2[tid] = bt2[tid];
    for (int i = tid; i < 32 * 64; i += 256) w2[i] = Wt2[i];
    __syncthreads();

    int gid = blockIdx.x * 256 + tid;
    float z = zenc[gid];
    float h[32];
#pragma unroll
    for (int j = 0; j < 32; j++) h[j] = fmaxf(fmaf(z, w1[j], bb1[j]), 0.f);

    float* er = e + (size_t)gid * EDIM;
#pragma unroll
    for (int k = 0; k < 64; k += 4) {
        float4 a = make_float4(bb2[k], bb2[k + 1], bb2[k + 2], bb2[k + 3]);
#pragma unroll
        for (int j = 0; j < 32; j++) {
            float hj = h[j];
            a.x = fmaf(hj, w2[j * 64 + k + 0], a.x);
            a.y = fmaf(hj, w2[j * 64 + k + 1], a.y);
            a.z = fmaf(hj, w2[j * 64 + k + 2], a.z);
            a.w = fmaf(hj, w2[j * 64 + k + 3], a.w);
        }
        *(float4*)(er + k) = a;
    }
}

// ================= VQ distance + argmin (codebook in smem, 2 rows/thread) ============
__global__ __launch_bounds__(256, 1) void vq_argmin_kernel(
    const float* __restrict__ e, const float* __restrict__ E, int* __restrict__ idx)
{
    extern __shared__ float sm[];
    float* sE = sm;                 // KC*EDIM
    float* ee = sm + KC * EDIM;     // KC
    const int tid = threadIdx.x;

    float4* sE4 = (float4*)sE;
    const float4* E4 = (const float4*)E;
    for (int i = tid; i < KC * EDIM / 4; i += 256) sE4[i] = E4[i];
    __syncthreads();
    for (int k = tid; k < KC; k += 256) {
        float s = 0.f;
        const float* row = sE + k * EDIM;
#pragma unroll 16
        for (int t = 0; t < EDIM; t++) s = fmaf(row[t], row[t], s);
        ee[k] = s;
    }
    __syncthreads();

    int r0 = (blockIdx.x * 256 + tid) * 2;
    float4 f0[16], f1[16];
    const float4* e0 = (const float4*)(e + (size_t)r0 * EDIM);
    const float4* e1 = (const float4*)(e + (size_t)(r0 + 1) * EDIM);
    float ff0 = 0.f, ff1 = 0.f;
#pragma unroll
    for (int t = 0; t < 16; t++) {
        f0[t] = e0[t]; f1[t] = e1[t];
        ff0 += f0[t].x * f0[t].x + f0[t].y * f0[t].y + f0[t].z * f0[t].z + f0[t].w * f0[t].w;
        ff1 += f1[t].x * f1[t].x + f1[t].y * f1[t].y + f1[t].z * f1[t].z + f1[t].w * f1[t].w;
    }

    float best0 = 3.4e38f, best1 = 3.4e38f;
    int bi0 = 0, bi1 = 0;
    for (int k = 0; k < KC; k++) {
        const float4* ek = sE4 + k * 16;
        float4 a0 = make_float4(0, 0, 0, 0), a1 = make_float4(0, 0, 0, 0);
#pragma unroll
        for (int t = 0; t < 16; t++) {
            float4 ev = ek[t];
            a0.x = fmaf(f0[t].x, ev.x, a0.x); a0.y = fmaf(f0[t].y, ev.y, a0.y);
            a0.z = fmaf(f0[t].z, ev.z, a0.z); a0.w = fmaf(f0[t].w, ev.w, a0.w);
            a1.x = fmaf(f1[t].x, ev.x, a1.x); a1.y = fmaf(f1[t].y, ev.y, a1.y);
            a1.z = fmaf(f1[t].z, ev.z, a1.z); a1.w = fmaf(f1[t].w, ev.w, a1.w);
        }
        float d0 = ff0 + ee[k] - 2.f * (a0.x + a0.y + a0.z + a0.w);
        float d1 = ff1 + ee[k] - 2.f * (a1.x + a1.y + a1.z + a1.w);
        if (d0 < best0) { best0 = d0; bi0 = k; }
        if (d1 < best1) { best1 = d1; bi1 = k; }
    }
    idx[r0] = bi0;
    idx[r0 + 1] = bi1;
}

// ================= init (per-replay scratch reset) =================
__global__ void init_kernel() {
    int i = blockIdx.x * blockDim.x + threadIdx.x;
    if (i < KC) g_counts[i] = 0.f;
}

// ================= gather q, counts, loss partials; mirror q into d_out ============
__global__ __launch_bounds__(256) void gather_kernel(
    const float* __restrict__ e, const float* __restrict__ E,
    const int* __restrict__ idx, float* __restrict__ q_aligned,
    float* __restrict__ q_out, float* __restrict__ counts,
    float* __restrict__ partial)
{
    const int tid = threadIdx.x;
    int r = blockIdx.x * 256 + tid;
    int k = idx[r];
    atomicAdd(&counts[k], 1.0f);

    const float4* Er = (const float4*)(E + (size_t)k * EDIM);
    const float4* er = (const float4*)(e + (size_t)r * EDIM);
    float4* qa = (float4*)(q_aligned + (size_t)r * EDIM);
    float* qo = q_out + (size_t)r * EDIM;

    float s = 0.f;
#pragma unroll
    for (int t = 0; t < 16; t++) {
        float4 qv = Er[t];
        float4 ev = er[t];
        qa[t] = qv;
        qo[t * 4 + 0] = qv.x; qo[t * 4 + 1] = qv.y;
        qo[t * 4 + 2] = qv.z; qo[t * 4 + 3] = qv.w;
        float dx = qv.x - ev.x, dy = qv.y - ev.y, dz = qv.z - ev.z, dw = qv.w - ev.w;
        s += dx * dx + dy * dy + dz * dz + dw * dw;
    }

    __shared__ float red[256];
    red[tid] = s;
    __syncthreads();
    for (int off = 128; off > 0; off >>= 1) {
        if (tid < off) red[tid] += red[tid + off];
        __syncthreads();
    }
    if (tid == 0) partial[blockIdx.x] = red[0];
}

// ================= scalars: vq_loss + perplexity =================
__global__ __launch_bounds__(512) void finalize_kernel(
    const float* __restrict__ partial, const float* __restrict__ counts,
    float* __restrict__ out)
{
    __shared__ float red[512];
    const int tid = threadIdx.x;
    red[tid] = partial[tid] + partial[tid + 512];
    __syncthreads();
    for (int off = 256; off > 0; off >>= 1) {
        if (tid < off) red[tid] += red[tid + off];
        __syncthreads();
    }
    if (tid == 0) out[OFF_VQ] = 1.25f * red[0] / (float)((size_t)NROWS * EDIM);
    __syncthreads();

    float p = counts[tid] * (1.0f / (float)NROWS);
    red[tid] = p * logf(p + 1e-10f);
    __syncthreads();
    for (int off = 256; off > 0; off >>= 1) {
        if (tid < off) red[tid] += red[tid + off];
        __syncthreads();
    }
    if (tid == 0) out[OFF_PPL] = expf(-red[0]);
}

// ================= classifier head: sigmoid(q @ Wc + bc), N=10 =================
__global__ __launch_bounds__(256) void cls_kernel(
    const float* __restrict__ q, const float* __restrict__ Wc,
    const float* __restrict__ bc, float* __restrict__ out)
{
    const int tid = threadIdx.x;
    const int b = blockIdx.x;
    const float* qr = q + (size_t)b * QDIM;
    float acc[10];
#pragma unroll
    for (int c = 0; c < 10; c++) acc[c] = 0.f;

    for (int i = tid; i < QDIM; i += 256) {
        float qv = qr[i];
        const float* w = Wc + (size_t)i * 10;
#pragma unroll
        for (int c = 0; c < 10; c++) acc[c] = fmaf(qv, w[c], acc[c]);
    }
    __shared__ float red[256];
#pragma unroll
    for (int c = 0; c < 10; c++) {
        red[tid] = acc[c];
        __syncthreads();
        for (int off = 128; off > 0; off >>= 1) {
            if (tid < off) red[tid] += red[tid + off];
            __syncthreads();
        }
        if (tid == 0) {
            float v = red[0] + bc[c];
            out[(size_t)b * 10 + c] = 1.0f / (1.0f + expf(-v));
        }
        __syncthreads();
    }
}

// =====================================================================
static float* symaddr(const void* sym) {
    void* p = nullptr;
    cudaGetSymbolAddress(&p, sym);
    return (float*)p;
}

extern "C" void kernel_launch(void* const* d_in, const int* in_sizes, int n_in,
                              void* d_out, int out_size)
{
    const float* x    = (const float*)d_in[0];
    const float* We1  = (const float*)d_in[1];
    const float* be1  = (const float*)d_in[2];
    const float* We2  = (const float*)d_in[3];
    const float* be2  = (const float*)d_in[4];
    const float* Wre1 = (const float*)d_in[5];
    const float* bre1 = (const float*)d_in[6];
    const float* Wre2 = (const float*)d_in[7];
    const float* bre2 = (const float*)d_in[8];
    const float* ge   = (const float*)d_in[9];
    const float* bebn = (const float*)d_in[10];
    const float* E    = (const float*)d_in[11];
    const float* Wt1  = (const float*)d_in[12];
    const float* bt1  = (const float*)d_in[13];
    const float* Wt2  = (const float*)d_in[14];
    const float* bt2  = (const float*)d_in[15];
    const float* Wc   = (const float*)d_in[16];
    const float* bc   = (const float*)d_in[17];
    const float* Wp   = (const float*)d_in[18];
    const float* bp   = (const float*)d_in[19];
    const float* Wrd1 = (const float*)d_in[20];
    const float* brd1 = (const float*)d_in[21];
    const float* Wrd2 = (const float*)d_in[22];
    const float* brd2 = (const float*)d_in[23];
    const float* gd   = (const float*)d_in[24];
    const float* bdbn = (const float*)d_in[25];
    const float* Wd1  = (const float*)d_in[26];
    const float* bd1  = (const float*)d_in[27];
    const float* Wd2  = (const float*)d_in[28];
    const float* bd2  = (const float*)d_in[29];

    float* out = (float*)d_out;

    float* ph    = symaddr(g_h);
    float* pz0   = symaddr(g_z0);
    float* pe    = symaddr(g_e);
    float* pq    = symaddr(g_q);
    int*   pidx  = (int*)symaddr(g_idx);
    float* pcnt  = symaddr(g_counts);
    float* ppart = symaddr(g_part);
    float* psplit= symaddr(g_split);
    float* pd1   = symaddr(g_d1);
    float* pd2   = symaddr(g_d2);
    float* pd3   = symaddr(g_d3);

    // ---- Encoder ----
    // h = relu(x @ We1 + be1)   [512,4096]x[4096,2048]
    {
        dim3 grid(L1DIM / TN, BSZ / TM, 1);
        gemm_kernel<<<grid, 256>>>(x, We1, be1, ph, nullptr,
                                   BSZ, L1DIM, INDIM, INDIM, 1);
    }
    // z0 = relu(h @ We2 + be2)  [512,2048]x[2048,512], split-K x4
    {
        dim3 grid(DDIM / TN, BSZ / TM, 4);
        gemm_kernel<<<grid, 256>>>(ph, We2, be2, nullptr, psplit,
                                   BSZ, DDIM, L1DIM, L1DIM / 4, 1);
        splitk_reduce<<<(BSZ * DDIM + 255) / 256, 256>>>(psplit, be2, pz0,
                                                         BSZ * DDIM, DDIM, 4, 1);
    }
    // encoder resblock -> zenc (written straight into d_out zenc slot)
    resblock_kernel<<<BSZ, 256>>>(pz0, Wre1, bre1, Wre2, bre2, ge, bebn,
                                  out + OFF_ZENC);

    // ---- VQ ----
    expand_kernel<<<NROWS / 256, 256>>>(out + OFF_ZENC, Wt1, bt1, Wt2, bt2, pe);

    {
        int smem = (KC * EDIM + KC) * sizeof(float);
        cudaFuncSetAttribute(vq_argmin_kernel,
                             cudaFuncAttributeMaxDynamicSharedMemorySize, smem);
        vq_argmin_kernel<<<NROWS / 512, 256, smem>>>(pe, E, pidx);
    }

    init_kernel<<<2, 256>>>();
    gather_kernel<<<NROWS / 256, 256>>>(pe, E, pidx, pq, out + OFF_QST,
                                        pcnt, ppart);
    finalize_kernel<<<1, 512>>>(ppart, pcnt, out);

    cls_kernel<<<BSZ, 256>>>(pq, Wc, bc, out + OFF_CLS);

    // ---- Decoder ----
    // d1 = relu(q @ Wp + bp)  [512,32768]x[32768,512], split-K x8
    {
        dim3 grid(DDIM / TN, BSZ / TM, 8);
        gemm_kernel<<<grid, 256>>>(pq, Wp, bp, nullptr, psplit,
                                   BSZ, DDIM, QDIM, QDIM / 8, 1);
        splitk_reduce<<<(BSZ * DDIM + 255) / 256, 256>>>(psplit, bp, pd1,
                                                         BSZ * DDIM, DDIM, 8, 1);
    }
    // decoder resblock
    resblock_kernel<<<BSZ, 256>>>(pd1, Wrd1, brd1, Wrd2, brd2, gd, bdbn, pd2);
    // d3 = relu(d2 @ Wd1 + bd1)  [512,512]x[512,2048]
    {
        dim3 grid(L1DIM / TN, BSZ / TM, 1);
        gemm_kernel<<<grid, 256>>>(pd2, Wd1, bd1, pd3, nullptr,
                                   BSZ, L1DIM, DDIM, DDIM, 1);
    }
    // x_recon = relu(d3 @ Wd2 + bd2)  [512,2048]x[2048,4096]
    {
        dim3 grid(INDIM / TN, BSZ / TM, 1);
        gemm_kernel<<<grid, 256>>>(pd3, Wd2, bd2, out + OFF_XREC, nullptr,
                                   BSZ, INDIM, L1DIM, L1DIM, 1);
    }
}